// round 10
// baseline (speedup 1.0000x reference)
#include <cuda_runtime.h>
#include <cuda_bf16.h>

// EntNet forward, dead-code-eliminated (see prior rounds), fused into ONE
// persistent kernel with software grid barriers:
//   P1 s_q = F_q@query          (work-stolen, warp-per-row)
//   P2 column partials of dot(s_q,mn_j), ||mn_j||^2   (256 blocks)
//   P3 softmax -> c_j = p_j/||mn_j||                  (block 0)
//   P4 u = mn @ c               (work-stolen, warp-per-row, mn L2-hot)
//   P5 v = prelu(s_q + H@u)     (work-stolen)
//   P6 y = R @ v                (work-stolen) -> d_out
// 512 blocks x 256 threads, all co-resident (__launch_bounds__(256,4):
// <=64 regs -> >=4 blocks/SM -> 592 slots >= 512, barrier is deadlock-free).

#define D 4096
#define M 1024
#define L 8192
#define SPLITS 64
#define ROWS_PER 64         // D / SPLITS
#define GRID 512
#define TPB 256

__device__ float g_sq[D];
__device__ float g_u[D];
__device__ float g_v[D];
__device__ float g_c[M];
__device__ float g_pdotT[M * SPLITS];   // [j*SPLITS + s]
__device__ float g_pssT[M * SPLITS];

// barrier + work-queue state. All values return to 0 by end of each run
// (even barrier count; final releaser resets counters) -> graph-replay safe.
__device__ unsigned g_count;
__device__ volatile unsigned g_sense;
__device__ unsigned g_w_sq, g_w_u, g_w_v, g_w_y;

__device__ __forceinline__ float warp_reduce_sum(float v) {
#pragma unroll
    for (int o = 16; o > 0; o >>= 1) v += __shfl_down_sync(0xFFFFFFFFu, v, o);
    return v;
}
__device__ __forceinline__ float dot4(float4 a, float4 b) {
    return a.x * b.x + a.y * b.y + a.z * b.z + a.w * b.w;
}
__device__ __forceinline__ float4 ldcs4(const float4* p) { return __ldcs(p); }

__device__ __forceinline__ void grid_barrier(unsigned want, bool final_reset) {
    __syncthreads();
    if (threadIdx.x == 0) {
        __threadfence();
        unsigned old = atomicAdd(&g_count, 1);
        if (old == GRID - 1) {
            g_count = 0;
            if (final_reset) { g_w_sq = 0; g_w_u = 0; g_w_v = 0; g_w_y = 0; }
            __threadfence();
            g_sense = want;
        } else {
            while (g_sense != want) __nanosleep(32);
        }
        __threadfence();
    }
    __syncthreads();
}

__global__ __launch_bounds__(TPB, 4) void entnet_fused(
    const float* __restrict__ F,      // F_q [D,L]
    const float* __restrict__ q,      // query [L]
    const float* __restrict__ mn,     // memory_nodes [D,M]
    const float* __restrict__ Hm,     // H [D,D]
    const float* __restrict__ Rm,     // R [D,D]
    const float* __restrict__ a_out,  // [1]
    float* __restrict__ out)          // [D]
{
    int warp = threadIdx.x >> 5, lane = threadIdx.x & 31;
    __shared__ int sh_base;
    __shared__ float shq[ROWS_PER];
    __shared__ float s_red[8];
    __shared__ float s_b;

    const float4* q4 = reinterpret_cast<const float4*>(q);

    // ---------------- P1: s_q rows (work-stolen, 8 rows/grab) ---------------
    for (;;) {
        __syncthreads();
        if (threadIdx.x == 0) sh_base = (int)atomicAdd(&g_w_sq, 8u);
        __syncthreads();
        int base = sh_base;
        if (base >= D) break;
        int row = base + warp;
        const float4* Fr = reinterpret_cast<const float4*>(F + (size_t)row * L);
        float a0 = 0.f, a1 = 0.f, a2 = 0.f, a3 = 0.f;
#pragma unroll 4
        for (int k = 0; k < 64; k += 4) {
            int i0 = lane + (k + 0) * 32;
            int i1 = lane + (k + 1) * 32;
            int i2 = lane + (k + 2) * 32;
            int i3 = lane + (k + 3) * 32;
            float4 f0 = ldcs4(&Fr[i0]);
            float4 f1 = ldcs4(&Fr[i1]);
            float4 f2 = ldcs4(&Fr[i2]);
            float4 f3 = ldcs4(&Fr[i3]);
            a0 += dot4(f0, __ldg(&q4[i0]));
            a1 += dot4(f1, __ldg(&q4[i1]));
            a2 += dot4(f2, __ldg(&q4[i2]));
            a3 += dot4(f3, __ldg(&q4[i3]));
        }
        float acc = warp_reduce_sum((a0 + a1) + (a2 + a3));
        if (lane == 0) g_sq[row] = acc;
    }
    grid_barrier(1u, false);

    // ---------------- P2: column partials (blocks 0..255) -------------------
    if (blockIdx.x < 4 * SPLITS) {
        int b = blockIdx.x;
        int j = (b & 3) * 256 + threadIdx.x;
        int s = b >> 2;
        if (threadIdx.x < ROWS_PER) shq[threadIdx.x] = g_sq[s * ROWS_PER + threadIdx.x];
        __syncthreads();
        const float* base = mn + (size_t)s * ROWS_PER * M + j;
        float d0 = 0.f, d1 = 0.f, s0 = 0.f, s1 = 0.f;
#pragma unroll 8
        for (int d = 0; d < ROWS_PER; d += 2) {
            float v0 = base[(size_t)d * M];
            float v1 = base[(size_t)(d + 1) * M];
            d0 += v0 * shq[d];
            d1 += v1 * shq[d + 1];
            s0 += v0 * v0;
            s1 += v1 * v1;
        }
        g_pdotT[j * SPLITS + s] = d0 + d1;
        g_pssT [j * SPLITS + s] = s0 + s1;
    }
    grid_barrier(0u, false);

    // ---------------- P3: softmax + fold 1/norm (block 0) -------------------
    if (blockIdx.x == 0) {
        float tval[4], nrm[4];
#pragma unroll
        for (int k = 0; k < 4; k++) {
            int j = threadIdx.x * 4 + k;
            const float4* pd = reinterpret_cast<const float4*>(&g_pdotT[j * SPLITS]);
            const float4* ps = reinterpret_cast<const float4*>(&g_pssT [j * SPLITS]);
            float dot = 0.f, ss = 0.f;
#pragma unroll
            for (int s4 = 0; s4 < SPLITS / 4; s4++) {
                float4 dv = pd[s4];
                float4 sv = ps[s4];
                dot += (dv.x + dv.y) + (dv.z + dv.w);
                ss  += (sv.x + sv.y) + (sv.z + sv.w);
            }
            float n = fmaxf(sqrtf(ss), 1e-12f);
            nrm[k] = n;
            tval[k] = dot / n;
        }
        // block max
        float m = fmaxf(fmaxf(tval[0], tval[1]), fmaxf(tval[2], tval[3]));
#pragma unroll
        for (int o = 16; o > 0; o >>= 1) m = fmaxf(m, __shfl_down_sync(0xFFFFFFFFu, m, o));
        if (lane == 0) s_red[warp] = m;
        __syncthreads();
        if (warp == 0) {
            float x = (lane < 8) ? s_red[lane] : -1e30f;
#pragma unroll
            for (int o = 4; o > 0; o >>= 1) x = fmaxf(x, __shfl_down_sync(0xFFFFFFFFu, x, o));
            if (lane == 0) s_b = x;
        }
        __syncthreads();
        float tmax = s_b;
        float e[4];
        float loc = 0.f;
#pragma unroll
        for (int k = 0; k < 4; k++) { e[k] = expf(tval[k] - tmax); loc += e[k]; }
        float su = warp_reduce_sum(loc);
        __syncthreads();
        if (lane == 0) s_red[warp] = su;
        __syncthreads();
        if (warp == 0) {
            float x = (lane < 8) ? s_red[lane] : 0.f;
#pragma unroll
            for (int o = 4; o > 0; o >>= 1) x += __shfl_down_sync(0xFFFFFFFFu, x, o);
            if (lane == 0) s_b = x;
        }
        __syncthreads();
        float esum = s_b;
#pragma unroll
        for (int k = 0; k < 4; k++) {
            int j = threadIdx.x * 4 + k;
            g_c[j] = e[k] / (esum * nrm[k]);
        }
    }
    grid_barrier(1u, false);

    // ---------------- P4: u = mn @ c (work-stolen, mn L2-hot) ---------------
    {
        const float4* c4 = reinterpret_cast<const float4*>(g_c);
        for (;;) {
            __syncthreads();
            if (threadIdx.x == 0) sh_base = (int)atomicAdd(&g_w_u, 8u);
            __syncthreads();
            int base = sh_base;
            if (base >= D) break;
            int row = base + warp;
            const float4* r = reinterpret_cast<const float4*>(mn + (size_t)row * M);
            float a0 = 0.f, a1 = 0.f, a2 = 0.f, a3 = 0.f;
#pragma unroll
            for (int k = 0; k < 8; k += 4) {
                int i0 = lane + (k + 0) * 32;
                int i1 = lane + (k + 1) * 32;
                int i2 = lane + (k + 2) * 32;
                int i3 = lane + (k + 3) * 32;
                float4 m0 = r[i0];
                float4 m1 = r[i1];
                float4 m2 = r[i2];
                float4 m3 = r[i3];
                a0 += dot4(m0, __ldg(&c4[i0]));
                a1 += dot4(m1, __ldg(&c4[i1]));
                a2 += dot4(m2, __ldg(&c4[i2]));
                a3 += dot4(m3, __ldg(&c4[i3]));
            }
            float acc = warp_reduce_sum((a0 + a1) + (a2 + a3));
            if (lane == 0) g_u[row] = acc;
        }
    }
    grid_barrier(0u, false);

    // ---------------- P5: v = prelu(s_q + H@u) (work-stolen) ----------------
    {
        const float4* u4 = reinterpret_cast<const float4*>(g_u);
        for (;;) {
            __syncthreads();
            if (threadIdx.x == 0) sh_base = (int)atomicAdd(&g_w_v, 8u);
            __syncthreads();
            int base = sh_base;
            if (base >= D) break;
            int row = base + warp;
            const float4* Hr = reinterpret_cast<const float4*>(Hm + (size_t)row * D);
            float a0 = 0.f, a1 = 0.f, a2 = 0.f, a3 = 0.f;
#pragma unroll 4
            for (int k = 0; k < 32; k += 4) {
                int i0 = lane + (k + 0) * 32;
                int i1 = lane + (k + 1) * 32;
                int i2 = lane + (k + 2) * 32;
                int i3 = lane + (k + 3) * 32;
                float4 f0 = ldcs4(&Hr[i0]);
                float4 f1 = ldcs4(&Hr[i1]);
                float4 f2 = ldcs4(&Hr[i2]);
                float4 f3 = ldcs4(&Hr[i3]);
                a0 += dot4(f0, __ldg(&u4[i0]));
                a1 += dot4(f1, __ldg(&u4[i1]));
                a2 += dot4(f2, __ldg(&u4[i2]));
                a3 += dot4(f3, __ldg(&u4[i3]));
            }
            float acc = warp_reduce_sum((a0 + a1) + (a2 + a3));
            if (lane == 0) {
                float x = g_sq[row] + acc;
                float a = __ldg(a_out);
                g_v[row] = (x >= 0.f) ? x : a * x;
            }
        }
    }
    grid_barrier(1u, false);

    // ---------------- P6: y = R @ v (work-stolen) -> out --------------------
    {
        const float4* v4 = reinterpret_cast<const float4*>(g_v);
        for (;;) {
            __syncthreads();
            if (threadIdx.x == 0) sh_base = (int)atomicAdd(&g_w_y, 8u);
            __syncthreads();
            int base = sh_base;
            if (base >= D) break;
            int row = base + warp;
            const float4* Rr = reinterpret_cast<const float4*>(Rm + (size_t)row * D);
            float a0 = 0.f, a1 = 0.f, a2 = 0.f, a3 = 0.f;
#pragma unroll 4
            for (int k = 0; k < 32; k += 4) {
                int i0 = lane + (k + 0) * 32;
                int i1 = lane + (k + 1) * 32;
                int i2 = lane + (k + 2) * 32;
                int i3 = lane + (k + 3) * 32;
                float4 f0 = ldcs4(&Rr[i0]);
                float4 f1 = ldcs4(&Rr[i1]);
                float4 f2 = ldcs4(&Rr[i2]);
                float4 f3 = ldcs4(&Rr[i3]);
                a0 += dot4(f0, __ldg(&v4[i0]));
                a1 += dot4(f1, __ldg(&v4[i1]));
                a2 += dot4(f2, __ldg(&v4[i2]));
                a3 += dot4(f3, __ldg(&v4[i3]));
            }
            float acc = warp_reduce_sum((a0 + a1) + (a2 + a3));
            if (lane == 0) out[row] = acc;
        }
    }
    // final barrier: resets work counters, returns g_sense to 0 (replay-safe)
    grid_barrier(0u, true);
}

extern "C" void kernel_launch(void* const* d_in, const int* in_sizes, int n_in,
                              void* d_out, int out_size) {
    // metadata order: input, query, F_i, F_q, keys, memory_nodes, U, V, W, R, H, a_mem, a_out
    const float* query = (const float*)d_in[1];
    const float* F_q   = (const float*)d_in[3];
    const float* mn    = (const float*)d_in[5];
    const float* Rm    = (const float*)d_in[9];
    const float* Hm    = (const float*)d_in[10];
    const float* a_out = (const float*)d_in[12];
    float* out = (float*)d_out;

    entnet_fused<<<GRID, TPB>>>(F_q, query, mn, Hm, Rm, a_out, out);
}

// round 11
// speedup vs baseline: 1.0820x; 1.0820x over previous
#include <cuda_runtime.h>
#include <cuda_bf16.h>

// EntNet forward, dead-code-eliminated (see prior rounds). 6-kernel structure
// (R5 = best) + per-warp dynamic row stealing (atomicAdd grab, no barriers),
// grid 592 = 148 SMs x 4 blocks for exact per-SM block balance.
// Row counters self-reset across graph replays via stream-ordered chain:
//   k_softmax -> ctr_sq, k_v -> ctr_u, k_y -> ctr_v, k_sq -> ctr_y.

#define D 4096
#define M 1024
#define L 8192
#define SPLITS 32
#define ROWS_PER 128        // D / SPLITS
#define GRID 592            // 148 * 4
#define TPB 256

__device__ float g_sq[D];
__device__ float g_u[D];
__device__ float g_v[D];
__device__ float g_c[M];
__device__ float g_pdot[SPLITS * M];
__device__ float g_pss[SPLITS * M];

__device__ unsigned g_ctr_sq, g_ctr_u, g_ctr_v, g_ctr_y;

__device__ __forceinline__ float warp_reduce_sum(float v) {
#pragma unroll
    for (int o = 16; o > 0; o >>= 1) v += __shfl_down_sync(0xFFFFFFFFu, v, o);
    return v;
}
__device__ __forceinline__ float dot4(float4 a, float4 b) {
    return a.x * b.x + a.y * b.y + a.z * b.z + a.w * b.w;
}
__device__ __forceinline__ float4 ldcs4(const float4* p) { return __ldcs(p); }

__device__ __forceinline__ int grab_row(unsigned* ctr, int lane) {
    unsigned r = 0;
    if (lane == 0) r = atomicAdd(ctr, 1u);
    return (int)__shfl_sync(0xFFFFFFFFu, r, 0);
}

// ---------------------------------------------------------------------------
// K1: s_q[d] = dot(F_q[d,:], query) — warp-per-row, dynamic grab, 64 f4/lane
// ---------------------------------------------------------------------------
__global__ __launch_bounds__(TPB) void k_sq(const float* __restrict__ F,
                                            const float* __restrict__ q) {
    if (blockIdx.x == 0 && threadIdx.x == 0) g_ctr_y = 0;  // reset for this replay's k_y
    int lane = threadIdx.x & 31;
    const float4* q4 = reinterpret_cast<const float4*>(q);
    for (;;) {
        int row = grab_row(&g_ctr_sq, lane);
        if (row >= D) break;
        const float4* Fr = reinterpret_cast<const float4*>(F + (size_t)row * L);
        float a0 = 0.f, a1 = 0.f, a2 = 0.f, a3 = 0.f;
#pragma unroll 4
        for (int k = 0; k < 64; k += 4) {
            int i0 = lane + (k + 0) * 32;
            int i1 = lane + (k + 1) * 32;
            int i2 = lane + (k + 2) * 32;
            int i3 = lane + (k + 3) * 32;
            float4 f0 = ldcs4(&Fr[i0]);
            float4 f1 = ldcs4(&Fr[i1]);
            float4 f2 = ldcs4(&Fr[i2]);
            float4 f3 = ldcs4(&Fr[i3]);
            a0 += dot4(f0, __ldg(&q4[i0]));
            a1 += dot4(f1, __ldg(&q4[i1]));
            a2 += dot4(f2, __ldg(&q4[i2]));
            a3 += dot4(f3, __ldg(&q4[i3]));
        }
        float acc = warp_reduce_sum((a0 + a1) + (a2 + a3));
        if (lane == 0) g_sq[row] = acc;
    }
}

// ---------------------------------------------------------------------------
// K2: per-column partial dot(s_q, mn[:,j]) and sum-of-squares over a D-slice.
// default caching: warms L2 with mn for k_u.
// ---------------------------------------------------------------------------
__global__ __launch_bounds__(256) void k_colpart(const float* __restrict__ mn) {
    int j = blockIdx.x * 256 + threadIdx.x;   // 4 x-blocks cover M=1024
    int s = blockIdx.y;                       // 32 slices of 128 rows
    __shared__ float shq[ROWS_PER];
    if (threadIdx.x < ROWS_PER) shq[threadIdx.x] = g_sq[s * ROWS_PER + threadIdx.x];
    __syncthreads();

    const float* base = mn + (size_t)s * ROWS_PER * M + j;
    float d0 = 0.f, d1 = 0.f, s0 = 0.f, s1 = 0.f;
#pragma unroll 8
    for (int d = 0; d < ROWS_PER; d += 2) {
        float v0 = base[(size_t)d * M];
        float v1 = base[(size_t)(d + 1) * M];
        d0 += v0 * shq[d];
        d1 += v1 * shq[d + 1];
        s0 += v0 * v0;
        s1 += v1 * v1;
    }
    g_pdot[s * M + j] = d0 + d1;
    g_pss [s * M + j] = s0 + s1;
}

// ---------------------------------------------------------------------------
// K3: reduce partials, softmax over M, fold 1/norm into c_j = p_j / ||mn_j||.
// Also resets ctr_sq for the next replay.
// ---------------------------------------------------------------------------
__global__ __launch_bounds__(1024) void k_softmax() {
    if (threadIdx.x == 0) g_ctr_sq = 0;
    int j = threadIdx.x;
    float dot = 0.f, ss = 0.f;
#pragma unroll
    for (int s = 0; s < SPLITS; ++s) {
        dot += g_pdot[s * M + j];
        ss  += g_pss [s * M + j];
    }
    float norm = fmaxf(sqrtf(ss), 1e-12f);
    float t = dot / norm;

    __shared__ float red[32];
    __shared__ float bcast;
    int lane = j & 31, wid = j >> 5;

    float m = t;
#pragma unroll
    for (int o = 16; o > 0; o >>= 1) m = fmaxf(m, __shfl_down_sync(0xFFFFFFFFu, m, o));
    if (lane == 0) red[wid] = m;
    __syncthreads();
    if (wid == 0) {
        float x = red[lane];
#pragma unroll
        for (int o = 16; o > 0; o >>= 1) x = fmaxf(x, __shfl_down_sync(0xFFFFFFFFu, x, o));
        if (lane == 0) bcast = x;
    }
    __syncthreads();
    float tmax = bcast;

    float e = expf(t - tmax);

    float su = warp_reduce_sum(e);
    __syncthreads();
    if (lane == 0) red[wid] = su;
    __syncthreads();
    if (wid == 0) {
        float x = red[lane];
        x = warp_reduce_sum(x);
        if (lane == 0) bcast = x;
    }
    __syncthreads();
    float esum = bcast;

    g_c[j] = e / (esum * norm);
}

// ---------------------------------------------------------------------------
// K4: u[d] = dot(mn[d,:], c) — warp-per-row dynamic grab, mn L2-hot
// ---------------------------------------------------------------------------
__global__ __launch_bounds__(TPB) void k_u(const float* __restrict__ mn) {
    int lane = threadIdx.x & 31;
    const float4* c4 = reinterpret_cast<const float4*>(g_c);
    for (;;) {
        int row = grab_row(&g_ctr_u, lane);
        if (row >= D) break;
        const float4* r = reinterpret_cast<const float4*>(mn + (size_t)row * M);
        float a0 = 0.f, a1 = 0.f, a2 = 0.f, a3 = 0.f;
        int i0 = lane,       i1 = lane + 32,  i2 = lane + 64,  i3 = lane + 96;
        int i4 = lane + 128, i5 = lane + 160, i6 = lane + 192, i7 = lane + 224;
        float4 m0 = r[i0];
        float4 m1 = r[i1];
        float4 m2 = r[i2];
        float4 m3 = r[i3];
        float4 m4 = r[i4];
        float4 m5 = r[i5];
        float4 m6 = r[i6];
        float4 m7 = r[i7];
        a0 += dot4(m0, __ldg(&c4[i0]));
        a1 += dot4(m1, __ldg(&c4[i1]));
        a2 += dot4(m2, __ldg(&c4[i2]));
        a3 += dot4(m3, __ldg(&c4[i3]));
        a0 += dot4(m4, __ldg(&c4[i4]));
        a1 += dot4(m5, __ldg(&c4[i5]));
        a2 += dot4(m6, __ldg(&c4[i6]));
        a3 += dot4(m7, __ldg(&c4[i7]));
        float acc = warp_reduce_sum((a0 + a1) + (a2 + a3));
        if (lane == 0) g_u[row] = acc;
    }
}

// ---------------------------------------------------------------------------
// K5: v[d] = prelu(s_q[d] + dot(H[d,:], u), a_out) — dynamic grab, 32 f4/lane
// Also resets ctr_u.
// ---------------------------------------------------------------------------
__global__ __launch_bounds__(TPB) void k_v(const float* __restrict__ H,
                                           const float* __restrict__ a_out) {
    if (blockIdx.x == 0 && threadIdx.x == 0) g_ctr_u = 0;
    int lane = threadIdx.x & 31;
    const float4* u4 = reinterpret_cast<const float4*>(g_u);
    for (;;) {
        int row = grab_row(&g_ctr_v, lane);
        if (row >= D) break;
        const float4* Hr = reinterpret_cast<const float4*>(H + (size_t)row * D);
        float a0 = 0.f, a1 = 0.f, a2 = 0.f, a3 = 0.f;
#pragma unroll 4
        for (int k = 0; k < 32; k += 4) {
            int i0 = lane + (k + 0) * 32;
            int i1 = lane + (k + 1) * 32;
            int i2 = lane + (k + 2) * 32;
            int i3 = lane + (k + 3) * 32;
            float4 f0 = ldcs4(&Hr[i0]);
            float4 f1 = ldcs4(&Hr[i1]);
            float4 f2 = ldcs4(&Hr[i2]);
            float4 f3 = ldcs4(&Hr[i3]);
            a0 += dot4(f0, __ldg(&u4[i0]));
            a1 += dot4(f1, __ldg(&u4[i1]));
            a2 += dot4(f2, __ldg(&u4[i2]));
            a3 += dot4(f3, __ldg(&u4[i3]));
        }
        float acc = warp_reduce_sum((a0 + a1) + (a2 + a3));
        if (lane == 0) {
            float x = g_sq[row] + acc;
            float a = __ldg(a_out);
            g_v[row] = (x >= 0.f) ? x : a * x;
        }
    }
}

// ---------------------------------------------------------------------------
// K6: y[d] = dot(R[d,:], v) — dynamic grab, 32 f4/lane -> d_out. Resets ctr_v.
// ---------------------------------------------------------------------------
__global__ __launch_bounds__(TPB) void k_y(const float* __restrict__ R,
                                           float* __restrict__ out) {
    if (blockIdx.x == 0 && threadIdx.x == 0) g_ctr_v = 0;
    int lane = threadIdx.x & 31;
    const float4* v4 = reinterpret_cast<const float4*>(g_v);
    for (;;) {
        int row = grab_row(&g_ctr_y, lane);
        if (row >= D) break;
        const float4* Rr = reinterpret_cast<const float4*>(R + (size_t)row * D);
        float a0 = 0.f, a1 = 0.f, a2 = 0.f, a3 = 0.f;
#pragma unroll 4
        for (int k = 0; k < 32; k += 4) {
            int i0 = lane + (k + 0) * 32;
            int i1 = lane + (k + 1) * 32;
            int i2 = lane + (k + 2) * 32;
            int i3 = lane + (k + 3) * 32;
            float4 f0 = ldcs4(&Rr[i0]);
            float4 f1 = ldcs4(&Rr[i1]);
            float4 f2 = ldcs4(&Rr[i2]);
            float4 f3 = ldcs4(&Rr[i3]);
            a0 += dot4(f0, __ldg(&v4[i0]));
            a1 += dot4(f1, __ldg(&v4[i1]));
            a2 += dot4(f2, __ldg(&v4[i2]));
            a3 += dot4(f3, __ldg(&v4[i3]));
        }
        float acc = warp_reduce_sum((a0 + a1) + (a2 + a3));
        if (lane == 0) out[row] = acc;
    }
}

extern "C" void kernel_launch(void* const* d_in, const int* in_sizes, int n_in,
                              void* d_out, int out_size) {
    // metadata order: input, query, F_i, F_q, keys, memory_nodes, U, V, W, R, H, a_mem, a_out
    const float* query = (const float*)d_in[1];
    const float* F_q   = (const float*)d_in[3];
    const float* mn    = (const float*)d_in[5];
    const float* Rm    = (const float*)d_in[9];
    const float* Hm    = (const float*)d_in[10];
    const float* a_out = (const float*)d_in[12];
    float* out = (float*)d_out;

    k_sq<<<GRID, TPB>>>(F_q, query);
    dim3 g2(M / 256, SPLITS);
    k_colpart<<<g2, 256>>>(mn);
    k_softmax<<<1, 1024>>>();
    k_u<<<GRID, TPB>>>(mn);
    k_v<<<GRID, TPB>>>(Hm, a_out);
    k_y<<<GRID, TPB>>>(Rm, out);
}

// round 13
// speedup vs baseline: 1.3056x; 1.2067x over previous
#include <cuda_runtime.h>
#include <cuda_bf16.h>

// EntNet forward, dead-code-eliminated (see prior rounds).
// R5 structure (best measured: 65.6us) with ONE change: 8-deep load batches
// in the big matvecs (k_sq, k_v, k_y) to double per-warp in-flight bytes.
// Static warp-per-row, 512 blocks x 256 threads, HW scheduling.

#define D 4096
#define M 1024
#define L 8192
#define SPLITS 32
#define ROWS_PER 128        // D / SPLITS

__device__ float g_sq[D];
__device__ float g_u[D];
__device__ float g_v[D];
__device__ float g_c[M];
__device__ float g_pdot[SPLITS * M];
__device__ float g_pss[SPLITS * M];

__device__ __forceinline__ float warp_reduce_sum(float v) {
#pragma unroll
    for (int o = 16; o > 0; o >>= 1) v += __shfl_down_sync(0xFFFFFFFFu, v, o);
    return v;
}
__device__ __forceinline__ float dot4(float4 a, float4 b) {
    return a.x * b.x + a.y * b.y + a.z * b.z + a.w * b.w;
}
__device__ __forceinline__ float4 ldcs4(const float4* p) { return __ldcs(p); }

// ---------------------------------------------------------------------------
// K1: s_q[d] = dot(F_q[d,:], query) — warp-per-row, 64 f4/lane, 8-deep batches
// ---------------------------------------------------------------------------
__global__ __launch_bounds__(256) void k_sq(const float* __restrict__ F,
                                            const float* __restrict__ q) {
    int warp = threadIdx.x >> 5, lane = threadIdx.x & 31;
    int row = blockIdx.x * 8 + warp;
    const float4* Fr = reinterpret_cast<const float4*>(F + (size_t)row * L);
    const float4* q4 = reinterpret_cast<const float4*>(q);
    float a0 = 0.f, a1 = 0.f, a2 = 0.f, a3 = 0.f;
    float4 f[8];
#pragma unroll
    for (int k = 0; k < 64; k += 8) {
#pragma unroll
        for (int i = 0; i < 8; i++)
            f[i] = ldcs4(&Fr[lane + (k + i) * 32]);
#pragma unroll
        for (int i = 0; i < 8; i++) {
            float4 qv = __ldg(&q4[lane + (k + i) * 32]);
            if ((i & 3) == 0) a0 += dot4(f[i], qv);
            else if ((i & 3) == 1) a1 += dot4(f[i], qv);
            else if ((i & 3) == 2) a2 += dot4(f[i], qv);
            else a3 += dot4(f[i], qv);
        }
    }
    float acc = warp_reduce_sum((a0 + a1) + (a2 + a3));
    if (lane == 0) g_sq[row] = acc;
}

// ---------------------------------------------------------------------------
// K2: per-column partial dot(s_q, mn[:,j]) and sum-of-squares over a D-slice.
// default caching: warms L2 with mn for k_u.
// ---------------------------------------------------------------------------
__global__ __launch_bounds__(256) void k_colpart(const float* __restrict__ mn) {
    int j = blockIdx.x * 256 + threadIdx.x;   // 4 x-blocks cover M=1024
    int s = blockIdx.y;                       // 32 slices of 128 rows
    __shared__ float shq[ROWS_PER];
    if (threadIdx.x < ROWS_PER) shq[threadIdx.x] = g_sq[s * ROWS_PER + threadIdx.x];
    __syncthreads();

    const float* base = mn + (size_t)s * ROWS_PER * M + j;
    float d0 = 0.f, d1 = 0.f, s0 = 0.f, s1 = 0.f;
#pragma unroll 8
    for (int d = 0; d < ROWS_PER; d += 2) {
        float v0 = base[(size_t)d * M];
        float v1 = base[(size_t)(d + 1) * M];
        d0 += v0 * shq[d];
        d1 += v1 * shq[d + 1];
        s0 += v0 * v0;
        s1 += v1 * v1;
    }
    g_pdot[s * M + j] = d0 + d1;
    g_pss [s * M + j] = s0 + s1;
}

// ---------------------------------------------------------------------------
// K3: reduce partials, softmax over M, fold 1/norm into c_j = p_j / ||mn_j||.
// ---------------------------------------------------------------------------
__global__ __launch_bounds__(1024) void k_softmax() {
    int j = threadIdx.x;
    float dot = 0.f, ss = 0.f;
#pragma unroll
    for (int s = 0; s < SPLITS; ++s) {
        dot += g_pdot[s * M + j];
        ss  += g_pss [s * M + j];
    }
    float norm = fmaxf(sqrtf(ss), 1e-12f);
    float t = dot / norm;

    __shared__ float red[32];
    __shared__ float bcast;
    int lane = j & 31, wid = j >> 5;

    float m = t;
#pragma unroll
    for (int o = 16; o > 0; o >>= 1) m = fmaxf(m, __shfl_down_sync(0xFFFFFFFFu, m, o));
    if (lane == 0) red[wid] = m;
    __syncthreads();
    if (wid == 0) {
        float x = red[lane];
#pragma unroll
        for (int o = 16; o > 0; o >>= 1) x = fmaxf(x, __shfl_down_sync(0xFFFFFFFFu, x, o));
        if (lane == 0) bcast = x;
    }
    __syncthreads();
    float tmax = bcast;

    float e = expf(t - tmax);

    float su = warp_reduce_sum(e);
    __syncthreads();
    if (lane == 0) red[wid] = su;
    __syncthreads();
    if (wid == 0) {
        float x = red[lane];
        x = warp_reduce_sum(x);
        if (lane == 0) bcast = x;
    }
    __syncthreads();
    float esum = bcast;

    g_c[j] = e / (esum * norm);
}

// ---------------------------------------------------------------------------
// K4: u[d] = dot(mn[d,:], c) — warp-per-row, 8 f4/lane batched, mn L2-hot
// ---------------------------------------------------------------------------
__global__ __launch_bounds__(256) void k_u(const float* __restrict__ mn) {
    int warp = threadIdx.x >> 5, lane = threadIdx.x & 31;
    int row = blockIdx.x * 8 + warp;
    const float4* r  = reinterpret_cast<const float4*>(mn + (size_t)row * M);
    const float4* c4 = reinterpret_cast<const float4*>(g_c);
    float a0 = 0.f, a1 = 0.f, a2 = 0.f, a3 = 0.f;
    float4 m[8];
#pragma unroll
    for (int i = 0; i < 8; i++) m[i] = r[lane + i * 32];
#pragma unroll
    for (int i = 0; i < 8; i++) {
        float4 cv = __ldg(&c4[lane + i * 32]);
        if ((i & 3) == 0) a0 += dot4(m[i], cv);
        else if ((i & 3) == 1) a1 += dot4(m[i], cv);
        else if ((i & 3) == 2) a2 += dot4(m[i], cv);
        else a3 += dot4(m[i], cv);
    }
    float acc = warp_reduce_sum((a0 + a1) + (a2 + a3));
    if (lane == 0) g_u[row] = acc;
}

// ---------------------------------------------------------------------------
// K5: v[d] = prelu(s_q[d] + dot(H[d,:], u), a_out) — 32 f4/lane, 8-deep
// ---------------------------------------------------------------------------
__global__ __launch_bounds__(256) void k_v(const float* __restrict__ H,
                                           const float* __restrict__ a_out) {
    int warp = threadIdx.x >> 5, lane = threadIdx.x & 31;
    int row = blockIdx.x * 8 + warp;
    const float4* Hr = reinterpret_cast<const float4*>(H + (size_t)row * D);
    const float4* u4 = reinterpret_cast<const float4*>(g_u);
    float a0 = 0.f, a1 = 0.f, a2 = 0.f, a3 = 0.f;
    float4 f[8];
#pragma unroll
    for (int k = 0; k < 32; k += 8) {
#pragma unroll
        for (int i = 0; i < 8; i++)
            f[i] = ldcs4(&Hr[lane + (k + i) * 32]);
#pragma unroll
        for (int i = 0; i < 8; i++) {
            float4 uv = __ldg(&u4[lane + (k + i) * 32]);
            if ((i & 3) == 0) a0 += dot4(f[i], uv);
            else if ((i & 3) == 1) a1 += dot4(f[i], uv);
            else if ((i & 3) == 2) a2 += dot4(f[i], uv);
            else a3 += dot4(f[i], uv);
        }
    }
    float acc = warp_reduce_sum((a0 + a1) + (a2 + a3));
    if (lane == 0) {
        float x = g_sq[row] + acc;
        float a = __ldg(a_out);
        g_v[row] = (x >= 0.f) ? x : a * x;
    }
}

// ---------------------------------------------------------------------------
// K6: y[d] = dot(R[d,:], v) — 32 f4/lane, 8-deep -> d_out
// ---------------------------------------------------------------------------
__global__ __launch_bounds__(256) void k_y(const float* __restrict__ R,
                                           float* __restrict__ out) {
    int warp = threadIdx.x >> 5, lane = threadIdx.x & 31;
    int row = blockIdx.x * 8 + warp;
    const float4* Rr = reinterpret_cast<const float4*>(R + (size_t)row * D);
    const float4* v4 = reinterpret_cast<const float4*>(g_v);
    float a0 = 0.f, a1 = 0.f, a2 = 0.f, a3 = 0.f;
    float4 f[8];
#pragma unroll
    for (int k = 0; k < 32; k += 8) {
#pragma unroll
        for (int i = 0; i < 8; i++)
            f[i] = ldcs4(&Rr[lane + (k + i) * 32]);
#pragma unroll
        for (int i = 0; i < 8; i++) {
            float4 vv = __ldg(&v4[lane + (k + i) * 32]);
            if ((i & 3) == 0) a0 += dot4(f[i], vv);
            else if ((i & 3) == 1) a1 += dot4(f[i], vv);
            else if ((i & 3) == 2) a2 += dot4(f[i], vv);
            else a3 += dot4(f[i], vv);
        }
    }
    float acc = warp_reduce_sum((a0 + a1) + (a2 + a3));
    if (lane == 0) out[row] = acc;
}

extern "C" void kernel_launch(void* const* d_in, const int* in_sizes, int n_in,
                              void* d_out, int out_size) {
    // metadata order: input, query, F_i, F_q, keys, memory_nodes, U, V, W, R, H, a_mem, a_out
    const float* query = (const float*)d_in[1];
    const float* F_q   = (const float*)d_in[3];
    const float* mn    = (const float*)d_in[5];
    const float* Rm    = (const float*)d_in[9];
    const float* Hm    = (const float*)d_in[10];
    const float* a_out = (const float*)d_in[12];
    float* out = (float*)d_out;

    k_sq<<<D / 8, 256>>>(F_q, query);
    dim3 g2(M / 256, SPLITS);
    k_colpart<<<g2, 256>>>(mn);
    k_softmax<<<1, 1024>>>();
    k_u<<<D / 8, 256>>>(mn);
    k_v<<<D / 8, 256>>>(Hm, a_out);
    k_y<<<D / 8, 256>>>(Rm, out);
}